// round 4
// baseline (speedup 1.0000x reference)
#include <cuda_runtime.h>

#define EPSV 1e-5f
#define NGRAPH 256
#define MAXM 100096

#define BM 128
#define BN 128
#define BK 16
#define SAS 20  // padded smem row stride (words) -> conflict-free for mma frag loads

// ---------------- scratch (device globals; no allocations) ----------------
__device__ int   g_start[NGRAPH];
__device__ int   g_end[NGRAPH];
__device__ __align__(16) float g_scale1[NGRAPH * 512];
__device__ __align__(16) float g_shift1[NGRAPH * 512];
__device__ __align__(16) float g_scale2[NGRAPH * 256];
__device__ __align__(16) float g_shift2[NGRAPH * 256];
__device__ __align__(16) float g_scale3[256];
__device__ __align__(16) float g_shift3[256];
__device__ __align__(16) float g_scale4[NGRAPH * 256];
__device__ __align__(16) float g_shift4[NGRAPH * 256];
__device__ __align__(16) float g_scale5[NGRAPH * 256];
__device__ __align__(16) float g_shift5[NGRAPH * 256];
__device__ __align__(16) float g_part[128 * 512];
__device__ __align__(16) float g_s1[(size_t)MAXM * 256];
__device__ __align__(16) float g_s2[(size_t)MAXM * 256];

// id: 0 -> external pointer p, 1 -> g_s1, 2 -> g_s2
__device__ __forceinline__ const float* resolve_in(const float* p, int id) {
    if (id == 1) return g_s1;
    if (id == 2) return g_s2;
    return p;
}
__device__ __forceinline__ float* resolve_out(float* p, int id) {
    if (id == 1) return g_s1;
    if (id == 2) return g_s2;
    return p;
}
__device__ __forceinline__ const float* scale_tab(int layer) {
    switch (layer) {
        case 1: return g_scale1;
        case 2: return g_scale2;
        case 3: return g_scale3;
        case 4: return g_scale4;
        default: return g_scale5;
    }
}
__device__ __forceinline__ const float* shift_tab(int layer) {
    switch (layer) {
        case 1: return g_shift1;
        case 2: return g_shift2;
        case 3: return g_shift3;
        case 4: return g_shift4;
        default: return g_shift5;
    }
}
__device__ __forceinline__ float* scale_tab_w(int layer) {
    switch (layer) {
        case 1: return g_scale1;
        case 2: return g_scale2;
        case 3: return g_scale3;
        case 4: return g_scale4;
        default: return g_scale5;
    }
}
__device__ __forceinline__ float* shift_tab_w(int layer) {
    switch (layer) {
        case 1: return g_shift1;
        case 2: return g_shift2;
        case 3: return g_shift3;
        case 4: return g_shift4;
        default: return g_shift5;
    }
}

// ---------------- helpers ----------------
__device__ __forceinline__ unsigned f2tf32(float f) {
    unsigned r;
    asm("cvt.rna.tf32.f32 %0, %1;" : "=r"(r) : "f"(f));
    return r;
}

__device__ __forceinline__ void mma8(float c[4], const unsigned a[4], const unsigned b[2]) {
    asm volatile(
        "mma.sync.aligned.m16n8k8.row.col.f32.tf32.tf32.f32 "
        "{%0,%1,%2,%3}, {%4,%5,%6,%7}, {%8,%9}, {%0,%1,%2,%3};\n"
        : "+f"(c[0]), "+f"(c[1]), "+f"(c[2]), "+f"(c[3])
        : "r"(a[0]), "r"(a[1]), "r"(a[2]), "r"(a[3]), "r"(b[0]), "r"(b[1]));
}

// ---------------- segment bounds ----------------
__global__ void seg_bounds_init() {
    int t = threadIdx.x;
    if (t < NGRAPH) { g_start[t] = 0; g_end[t] = 0; }
}

__global__ void seg_bounds(const int* __restrict__ batch, int n) {
    int i = blockIdx.x * blockDim.x + threadIdx.x;
    if (i >= n) return;
    int g = batch[i];
    if (g < 0 || g >= NGRAPH) return;
    if (i == 0 || batch[i - 1] != g) g_start[g] = i;
    if (i == n - 1 || batch[i + 1] != g) g_end[g] = i + 1;
}

// ---------------- per-graph stats -> scale/shift ----------------
// one block per graph, blockDim = dim (256 or 512); thread owns one feature
__global__ void seg_stats(const float* xp, int x_id,
                          const float* __restrict__ w, const float* __restrict__ b,
                          const float* __restrict__ ms, int layer, int dim) {
    const float* __restrict__ x = resolve_in(xp, x_id);
    float* __restrict__ scale = scale_tab_w(layer);
    float* __restrict__ shift = shift_tab_w(layer);
    int g = blockIdx.x, t = threadIdx.x;
    int s0 = g_start[g], e0 = g_end[g];
    float s = 0.f, q = 0.f;
    for (int r = s0; r < e0; ++r) {
        float v = x[(size_t)r * dim + t];
        s += v;
        q += v * v;
    }
    float cnt = fmaxf((float)(e0 - s0), 1.f);
    float mean = s / cnt;
    float m2 = mean * ms[t];
    float var = q / cnt - 2.f * m2 * mean + m2 * m2;
    float sc = w[t] * rsqrtf(var + EPSV);
    scale[(size_t)g * dim + t] = sc;
    shift[(size_t)g * dim + t] = b[t] - m2 * sc;
}

// ---------------- global stats (gn3), deterministic 2-stage ----------------
__global__ void glob_partial(int x_id, int M) {
    const float* __restrict__ x = resolve_in(nullptr, x_id);
    int t = threadIdx.x;  // 0..255
    float s = 0.f, q = 0.f;
    for (int r = blockIdx.x; r < M; r += gridDim.x) {
        float v = x[(size_t)r * 256 + t];
        s += v;
        q += v * v;
    }
    g_part[blockIdx.x * 512 + t] = s;
    g_part[blockIdx.x * 512 + 256 + t] = q;
}

__global__ void glob_final(const float* __restrict__ w, const float* __restrict__ b,
                           const float* __restrict__ ms, int nb, int M) {
    int t = threadIdx.x;
    float s = 0.f, q = 0.f;
    for (int i = 0; i < nb; ++i) {
        s += g_part[i * 512 + t];
        q += g_part[i * 512 + 256 + t];
    }
    float mean = s / (float)M;
    float m2 = mean * ms[t];
    float var = q / (float)M - 2.f * m2 * mean + m2 * m2;
    float sc = w[t] * rsqrtf(var + EPSV);
    g_scale3[t] = sc;
    g_shift3[t] = b[t] - m2 * sc;
}

// ---------------- fused norm/prelu + tf32 GEMM + bias/residual epilogue ----------------
// out[m,n] = epilogue( sum_k f(A[m,k]) * W[n,k] + bias[n] )
// f(a) = prelu( a*scale[g,k] + shift[g,k] ),  g = batch[m] (gstride=0 -> global stats)
__global__ void gemm_tf32(const float* Ap, int A_id, const int* __restrict__ batch,
                          int layer, int gstride, const float* __restrict__ alphaP,
                          const float* __restrict__ W, const float* __restrict__ bias,
                          int res_id, float* outp, int out_id,
                          int M, int N, int K) {
    const float* __restrict__ A = resolve_in(Ap, A_id);
    const float* __restrict__ scale = scale_tab(layer);
    const float* __restrict__ shift = shift_tab(layer);
    const float* res = (res_id == 0) ? nullptr : resolve_in(nullptr, res_id);
    float* out = resolve_out(outp, out_id);

    __shared__ unsigned As[2][BM * SAS];
    __shared__ unsigned Bs[2][BN * SAS];
    __shared__ int rowg[BM];

    const int tid = threadIdx.x;
    const int bm = blockIdx.y * BM;
    const int bn = blockIdx.x * BN;
    const int lane = tid & 31;
    const int warp = tid >> 5;
    const int wm = (warp >> 1) * 32;  // 4 warps over M
    const int wn = (warp & 1) * 64;   // 2 warps over N
    const int qid = lane >> 2;
    const int tig = lane & 3;

    const bool use_prelu = (alphaP != nullptr);
    const float alpha = use_prelu ? *alphaP : 0.f;

    if (tid < BM) {
        int m = bm + tid;
        int g = (m < M) ? batch[m] : 0;
        rowg[tid] = (g >= 0 && g < NGRAPH) ? g : 0;
    }
    __syncthreads();

    float4 av[2], bv[2];

    auto fetch = [&](int kt) {
#pragma unroll
        for (int i = 0; i < 2; ++i) {
            int f4 = tid + i * 256;
            int r = f4 >> 2, c4 = f4 & 3;
            int k = kt * BK + c4 * 4;
            int m = bm + r;
            float4 v = make_float4(0.f, 0.f, 0.f, 0.f);
            if (m < M) v = *reinterpret_cast<const float4*>(A + (size_t)m * K + k);
            int g = rowg[r];
            float4 sc = *reinterpret_cast<const float4*>(scale + (size_t)g * gstride + k);
            float4 sh = *reinterpret_cast<const float4*>(shift + (size_t)g * gstride + k);
            float4 o;
            o.x = fmaf(v.x, sc.x, sh.x);
            o.y = fmaf(v.y, sc.y, sh.y);
            o.z = fmaf(v.z, sc.z, sh.z);
            o.w = fmaf(v.w, sc.w, sh.w);
            if (use_prelu) {
                o.x = o.x >= 0.f ? o.x : alpha * o.x;
                o.y = o.y >= 0.f ? o.y : alpha * o.y;
                o.z = o.z >= 0.f ? o.z : alpha * o.z;
                o.w = o.w >= 0.f ? o.w : alpha * o.w;
            }
            av[i] = o;
            int n = bn + r;  // N is a multiple of BN -> always valid
            bv[i] = *reinterpret_cast<const float4*>(W + (size_t)n * K + k);
        }
    };

    auto store = [&](int buf) {
#pragma unroll
        for (int i = 0; i < 2; ++i) {
            int f4 = tid + i * 256;
            int r = f4 >> 2, c4 = f4 & 3;
            uint4 pa, pb;
            pa.x = f2tf32(av[i].x); pa.y = f2tf32(av[i].y);
            pa.z = f2tf32(av[i].z); pa.w = f2tf32(av[i].w);
            pb.x = f2tf32(bv[i].x); pb.y = f2tf32(bv[i].y);
            pb.z = f2tf32(bv[i].z); pb.w = f2tf32(bv[i].w);
            *reinterpret_cast<uint4*>(&As[buf][r * SAS + c4 * 4]) = pa;
            *reinterpret_cast<uint4*>(&Bs[buf][r * SAS + c4 * 4]) = pb;
        }
    };

    float acc[2][8][4];
#pragma unroll
    for (int a = 0; a < 2; ++a)
#pragma unroll
        for (int b2 = 0; b2 < 8; ++b2)
#pragma unroll
            for (int c = 0; c < 4; ++c) acc[a][b2][c] = 0.f;

    auto compute = [&](int buf) {
#pragma unroll
        for (int kk = 0; kk < 2; ++kk) {
            unsigned a[2][4];
#pragma unroll
            for (int mt = 0; mt < 2; ++mt) {
                int row = wm + mt * 16 + qid;
                a[mt][0] = As[buf][row * SAS + kk * 8 + tig];
                a[mt][2] = As[buf][row * SAS + kk * 8 + tig + 4];
                a[mt][1] = As[buf][(row + 8) * SAS + kk * 8 + tig];
                a[mt][3] = As[buf][(row + 8) * SAS + kk * 8 + tig + 4];
            }
            unsigned bf[8][2];
#pragma unroll
            for (int nt = 0; nt < 8; ++nt) {
                int col = wn + nt * 8 + qid;
                bf[nt][0] = Bs[buf][col * SAS + kk * 8 + tig];
                bf[nt][1] = Bs[buf][col * SAS + kk * 8 + tig + 4];
            }
#pragma unroll
            for (int mt = 0; mt < 2; ++mt)
#pragma unroll
                for (int nt = 0; nt < 8; ++nt) mma8(acc[mt][nt], a[mt], bf[nt]);
        }
    };

    fetch(0);
    store(0);
    __syncthreads();
    const int KT = K / BK;
    for (int kt = 0; kt < KT; ++kt) {
        if (kt + 1 < KT) fetch(kt + 1);
        compute(kt & 1);
        if (kt + 1 < KT) store((kt + 1) & 1);
        __syncthreads();
    }

    // epilogue
#pragma unroll
    for (int mt = 0; mt < 2; ++mt) {
        int r0 = bm + wm + mt * 16 + qid;
        int r1 = r0 + 8;
#pragma unroll
        for (int nt = 0; nt < 8; ++nt) {
            int c = bn + wn + nt * 8 + tig * 2;
            float2 b2 = *reinterpret_cast<const float2*>(bias + c);
            if (r0 < M) {
                float v0 = acc[mt][nt][0] + b2.x;
                float v1 = acc[mt][nt][1] + b2.y;
                if (res) {
                    float2 rr = *reinterpret_cast<const float2*>(res + (size_t)r0 * N + c);
                    v0 = (v0 + rr.x) * 0.5f;
                    v1 = (v1 + rr.y) * 0.5f;
                }
                *reinterpret_cast<float2*>(out + (size_t)r0 * N + c) = make_float2(v0, v1);
            }
            if (r1 < M) {
                float v0 = acc[mt][nt][2] + b2.x;
                float v1 = acc[mt][nt][3] + b2.y;
                if (res) {
                    float2 rr = *reinterpret_cast<const float2*>(res + (size_t)r1 * N + c);
                    v0 = (v0 + rr.x) * 0.5f;
                    v1 = (v1 + rr.y) * 0.5f;
                }
                *reinterpret_cast<float2*>(out + (size_t)r1 * N + c) = make_float2(v0, v1);
            }
        }
    }
}

// ---------------- launch ----------------
extern "C" void kernel_launch(void* const* d_in, const int* in_sizes, int n_in,
                              void* d_out, int out_size) {
    const float* x = (const float*)d_in[0];
    const int* batch = (const int*)d_in[1];   // JAX default x64-disabled -> int32
    const float* gn1_w = (const float*)d_in[2];
    const float* gn1_b = (const float*)d_in[3];
    const float* gn1_ms = (const float*)d_in[4];
    const float* gn2_w = (const float*)d_in[5];
    const float* gn2_b = (const float*)d_in[6];
    const float* gn2_ms = (const float*)d_in[7];
    const float* gn3_w = (const float*)d_in[8];
    const float* gn3_b = (const float*)d_in[9];
    const float* gn3_ms = (const float*)d_in[10];
    const float* gn4_w = (const float*)d_in[11];
    const float* gn4_b = (const float*)d_in[12];
    const float* gn4_ms = (const float*)d_in[13];
    const float* gn5_w = (const float*)d_in[14];
    const float* gn5_b = (const float*)d_in[15];
    const float* gn5_ms = (const float*)d_in[16];
    const float* lin1_W = (const float*)d_in[17];
    const float* lin1_b = (const float*)d_in[18];
    const float* lin2_W = (const float*)d_in[19];
    const float* lin2_b = (const float*)d_in[20];
    const float* lin3_W = (const float*)d_in[21];
    const float* lin3_b = (const float*)d_in[22];
    const float* lin4_W = (const float*)d_in[23];
    const float* lin4_b = (const float*)d_in[24];
    const float* lin5_W = (const float*)d_in[25];
    const float* lin5_b = (const float*)d_in[26];
    const float* a2 = (const float*)d_in[27];
    const float* a3 = (const float*)d_in[28];
    const float* a4 = (const float*)d_in[29];
    const float* a5 = (const float*)d_in[30];

    const int M = in_sizes[0] / 512;

    seg_bounds_init<<<1, NGRAPH>>>();
    seg_bounds<<<(M + 255) / 256, 256>>>(batch, M);

    const int gy = (M + BM - 1) / BM;
    const dim3 thr(256);

    // layer 1: gn1 -> lin1   (x external -> s1)
    seg_stats<<<NGRAPH, 512>>>(x, 0, gn1_w, gn1_b, gn1_ms, 1, 512);
    gemm_tf32<<<dim3(2, gy), thr>>>(x, 0, batch, 1, 512, nullptr,
                                    lin1_W, lin1_b, 0, nullptr, 1,
                                    M, 256, 512);

    // layer 2: gn2 -> prelu -> lin2   (s1 -> s2)
    seg_stats<<<NGRAPH, 256>>>(nullptr, 1, gn2_w, gn2_b, gn2_ms, 2, 256);
    gemm_tf32<<<dim3(2, gy), thr>>>(nullptr, 1, batch, 2, 256, a2,
                                    lin2_W, lin2_b, 0, nullptr, 2,
                                    M, 256, 256);

    // layer 3: gn3 (global) -> prelu -> lin3, x2 = (h + x1)/2   (s2 -> s1, res s1)
    glob_partial<<<128, 256>>>(2, M);
    glob_final<<<1, 256>>>(gn3_w, gn3_b, gn3_ms, 128, M);
    gemm_tf32<<<dim3(2, gy), thr>>>(nullptr, 2, batch, 3, 0, a3,
                                    lin3_W, lin3_b, 1, nullptr, 1,
                                    M, 256, 256);

    // layer 4: gn4 -> prelu -> lin4, x3 = (h + x2)/2   (s1 -> s2, res s1)
    seg_stats<<<NGRAPH, 256>>>(nullptr, 1, gn4_w, gn4_b, gn4_ms, 4, 256);
    gemm_tf32<<<dim3(2, gy), thr>>>(nullptr, 1, batch, 4, 256, a4,
                                    lin4_W, lin4_b, 1, nullptr, 2,
                                    M, 256, 256);

    // layer 5: gn5 -> prelu -> lin5   (s2 -> d_out)
    seg_stats<<<NGRAPH, 256>>>(nullptr, 2, gn5_w, gn5_b, gn5_ms, 5, 256);
    gemm_tf32<<<dim3(4, gy), thr>>>(nullptr, 2, batch, 5, 256, a5,
                                    lin5_W, lin5_b, 0, (float*)d_out, 0,
                                    M, 512, 256);
}

// round 6
// speedup vs baseline: 1.1454x; 1.1454x over previous
#include <cuda_runtime.h>
#include <cstdint>

#define EPSV 1e-5f
#define NGRAPH 256
#define MAXM 100096

// Arch-specific ('a'/'f') device pass => tcgen05 available
#if defined(__CUDA_ARCH_SPECIFIC__) || defined(__CUDA_ARCH_FAMILY_SPECIFIC__) || defined(__CUDA_ARCH_FEAT_SM103_ALL)
#define TC5 1
#else
#define TC5 0
#endif

#define TM 128
#define TN 128
// tcgen05 path: TK=32, 2 stages x (A 16KB + B 16KB) = 64KB
#define TC_STAGE 32768
// fallback path: BK=16 double-buffered mma.sync tiles (40KB)
#define BK 16
#define SAS 20
#define DYN_SMEM (2 * TC_STAGE + 1024)

// idesc (kind::tf32): c=F32(1)@[4:5], a=TF32(2)@[7:9], b=TF32(2)@[10:12], N/8@[17:22], M/16@[24:28]
#define IDESC_TF32 ((1u << 4) | (2u << 7) | (2u << 10) | (16u << 17) | (8u << 24))

// ---------------- scratch (device globals; no allocations) ----------------
__device__ int g_start[NGRAPH];
__device__ int g_end[NGRAPH];
__device__ __align__(16) float g_scale1[NGRAPH * 512];
__device__ __align__(16) float g_shift1[NGRAPH * 512];
__device__ __align__(16) float g_scale2[NGRAPH * 256];
__device__ __align__(16) float g_shift2[NGRAPH * 256];
__device__ __align__(16) float g_scale3[256];
__device__ __align__(16) float g_shift3[256];
__device__ __align__(16) float g_scale4[NGRAPH * 256];
__device__ __align__(16) float g_shift4[NGRAPH * 256];
__device__ __align__(16) float g_scale5[NGRAPH * 256];
__device__ __align__(16) float g_shift5[NGRAPH * 256];
__device__ __align__(16) float g_part[128 * 512];
__device__ __align__(16) float g_part2[NGRAPH * 4 * 1024];
__device__ __align__(16) float g_s1[(size_t)MAXM * 256];
__device__ __align__(16) float g_s2[(size_t)MAXM * 256];

__device__ __forceinline__ const float* resolve_in(const float* p, int id) {
    if (id == 1) return g_s1;
    if (id == 2) return g_s2;
    return p;
}
__device__ __forceinline__ float* resolve_out(float* p, int id) {
    if (id == 1) return g_s1;
    if (id == 2) return g_s2;
    return p;
}
__device__ __forceinline__ const float* scale_tab(int layer) {
    switch (layer) {
        case 1: return g_scale1;
        case 2: return g_scale2;
        case 3: return g_scale3;
        case 4: return g_scale4;
        default: return g_scale5;
    }
}
__device__ __forceinline__ const float* shift_tab(int layer) {
    switch (layer) {
        case 1: return g_shift1;
        case 2: return g_shift2;
        case 3: return g_shift3;
        case 4: return g_shift4;
        default: return g_shift5;
    }
}
__device__ __forceinline__ float* scale_tab_w(int layer) {
    switch (layer) {
        case 1: return g_scale1;
        case 2: return g_scale2;
        case 3: return g_scale3;
        case 4: return g_scale4;
        default: return g_scale5;
    }
}
__device__ __forceinline__ float* shift_tab_w(int layer) {
    switch (layer) {
        case 1: return g_shift1;
        case 2: return g_shift2;
        case 3: return g_shift3;
        case 4: return g_shift4;
        default: return g_shift5;
    }
}

// ---------------- common helpers ----------------
__device__ __forceinline__ uint32_t smem_u32(const void* p) {
    uint32_t a;
    asm("{ .reg .u64 t; cvta.to.shared.u64 t, %1; cvt.u32.u64 %0, t; }" : "=r"(a) : "l"(p));
    return a;
}
__device__ __forceinline__ unsigned f2tf32(float f) {
    unsigned r;
    asm("cvt.rna.tf32.f32 %0, %1;" : "=r"(r) : "f"(f));
    return r;
}

#if TC5
// ---------------- tcgen05 helpers (arch-specific pass only) ----------------
static constexpr uint64_t SMEM_DESC_BASE_SW128 =
    (uint64_t(2) << 61) | (uint64_t(1) << 46) | (uint64_t(64) << 32) | (uint64_t(1) << 16);
#define MAKE_SMEM_DESC(addr) (SMEM_DESC_BASE_SW128 | ((uint64_t)((addr) >> 4) & 0x3FFF))

#define TCGEN05_ALLOC(sm, n) \
    asm volatile("tcgen05.alloc.cta_group::1.sync.aligned.shared::cta.b32 [%0], %1;" :: "r"(sm), "r"(n) : "memory")
#define TCGEN05_DEALLOC(t, n) \
    asm volatile("tcgen05.dealloc.cta_group::1.sync.aligned.b32 %0, %1;" :: "r"(t), "r"(n))
#define TCGEN05_RELINQ() \
    asm volatile("tcgen05.relinquish_alloc_permit.cta_group::1.sync.aligned;")
#define TCGEN05_COMMIT(mb) \
    asm volatile("tcgen05.commit.cta_group::1.mbarrier::arrive::one.shared::cluster.b64 [%0];" :: "r"(mb) : "memory")
#define TCGEN05_FENCE_AFTER() asm volatile("tcgen05.fence::after_thread_sync;" ::: "memory")
#define TCGEN05_FENCE_BEFORE() asm volatile("tcgen05.fence::before_thread_sync;" ::: "memory")
#define TCGEN05_WAIT_LD() asm volatile("tcgen05.wait::ld.sync.aligned;" ::: "memory")
#define MBARRIER_INIT(mb, c) \
    asm volatile("mbarrier.init.shared.b64 [%0], %1;" :: "r"(mb), "r"(c) : "memory")

#define MBARRIER_WAIT_PARITY(mb, par) do {                                            \
    uint32_t _mb = (mb), _pr = (par), _done;                                          \
    asm volatile("{\n\t.reg .pred p;\n\t"                                             \
                 "mbarrier.try_wait.parity.acquire.cta.shared::cta.b64 p, [%1], %2;\n\t" \
                 "selp.b32 %0, 1, 0, p;\n\t}"                                         \
                 : "=r"(_done) : "r"(_mb), "r"(_pr) : "memory");                      \
    if (!_done) {                                                                     \
        asm volatile("{\n\t.reg .pred P1;\n\t"                                        \
                     "WL_%=:\n\t"                                                     \
                     "mbarrier.try_wait.parity.acquire.cta.shared::cta.b64 P1, [%0], %1, 0x989680;\n\t" \
                     "@P1 bra.uni WD_%=;\n\t"                                         \
                     "bra.uni WL_%=;\n\t"                                             \
                     "WD_%=:\n\t}"                                                    \
                     :: "r"(_mb), "r"(_pr) : "memory");                               \
    }                                                                                 \
} while (0)

#define LDTM_X32(r, addr)                                                              \
    asm volatile("tcgen05.ld.sync.aligned.32x32b.x32.b32 "                             \
                 "{%0, %1, %2, %3, %4, %5, %6, %7, "                                   \
                 " %8, %9, %10, %11, %12, %13, %14, %15, "                             \
                 " %16, %17, %18, %19, %20, %21, %22, %23, "                           \
                 " %24, %25, %26, %27, %28, %29, %30, %31}, [%32];"                    \
                 : "=r"((r)[0]), "=r"((r)[1]), "=r"((r)[2]), "=r"((r)[3]),             \
                   "=r"((r)[4]), "=r"((r)[5]), "=r"((r)[6]), "=r"((r)[7]),             \
                   "=r"((r)[8]), "=r"((r)[9]), "=r"((r)[10]), "=r"((r)[11]),           \
                   "=r"((r)[12]), "=r"((r)[13]), "=r"((r)[14]), "=r"((r)[15]),         \
                   "=r"((r)[16]), "=r"((r)[17]), "=r"((r)[18]), "=r"((r)[19]),         \
                   "=r"((r)[20]), "=r"((r)[21]), "=r"((r)[22]), "=r"((r)[23]),         \
                   "=r"((r)[24]), "=r"((r)[25]), "=r"((r)[26]), "=r"((r)[27]),         \
                   "=r"((r)[28]), "=r"((r)[29]), "=r"((r)[30]), "=r"((r)[31])          \
                 : "r"(addr))

__device__ __forceinline__ void mma_tf32_ss(uint32_t d, uint64_t ad, uint64_t bd,
                                            uint32_t idesc, bool accum) {
    uint32_t en = accum ? 1u : 0u;
    asm volatile(
        "{\n\t.reg .pred p;\n\tsetp.ne.u32 p, %5, 0;\n\t"
        "tcgen05.mma.cta_group::1.kind::tf32 [%0], %1, %2, %3, {%4, %4, %4, %4}, p;\n\t}"
        :: "r"(d), "l"(ad), "l"(bd), "r"(idesc), "r"(0u), "r"(en) : "memory");
}

// swizzled byte offset in a 128-row x 32-col tf32 tile (SW128, atoms 8x128B)
__device__ __forceinline__ uint32_t tile_off32(int row, int kl) {
    uint32_t off = (uint32_t)((row >> 3) * 1024 + (row & 7) * 128 + kl * 4);
    return off ^ ((off >> 3) & 0x70);
}
#else
// ---------------- mma.sync helper (fallback pass) ----------------
__device__ __forceinline__ void mma8(float c[4], const unsigned a[4], const unsigned b[2]) {
    asm volatile(
        "mma.sync.aligned.m16n8k8.row.col.f32.tf32.tf32.f32 "
        "{%0,%1,%2,%3}, {%4,%5,%6,%7}, {%8,%9}, {%0,%1,%2,%3};\n"
        : "+f"(c[0]), "+f"(c[1]), "+f"(c[2]), "+f"(c[3])
        : "r"(a[0]), "r"(a[1]), "r"(a[2]), "r"(a[3]), "r"(b[0]), "r"(b[1]));
}
#endif

// ---------------- segment bounds ----------------
__global__ void seg_bounds_init() {
    int t = threadIdx.x;
    if (t < NGRAPH) { g_start[t] = 0; g_end[t] = 0; }
}

__global__ void seg_bounds(const int* __restrict__ batch, int n) {
    int i = blockIdx.x * blockDim.x + threadIdx.x;
    if (i >= n) return;
    int g = batch[i];
    if (g < 0 || g >= NGRAPH) return;
    if (i == 0 || batch[i - 1] != g) g_start[g] = i;
    if (i == n - 1 || batch[i + 1] != g) g_end[g] = i + 1;
}

// ---------------- per-graph stats: 4-way split partial + combine ----------------
__global__ void seg_stats_part(const float* xp, int x_id, int dim) {
    const float* __restrict__ x = resolve_in(xp, x_id);
    int g = blockIdx.x, part = blockIdx.y, t = threadIdx.x;
    int s0 = g_start[g], e0 = g_end[g];
    int len = e0 - s0;
    int chunk = (len + 3) >> 2;
    int r0 = s0 + part * chunk;
    int r1 = r0 + chunk; if (r1 > e0) r1 = e0;
    float s = 0.f, q = 0.f;
    for (int r = r0; r < r1; ++r) {
        float v = x[(size_t)r * dim + t];
        s += v;
        q += v * v;
    }
    size_t base = ((size_t)(g * 4 + part)) * 1024;
    g_part2[base + t] = s;
    g_part2[base + 512 + t] = q;
}

__global__ void seg_stats_final(const float* __restrict__ w, const float* __restrict__ b,
                                const float* __restrict__ ms, int layer, int dim) {
    float* __restrict__ scale = scale_tab_w(layer);
    float* __restrict__ shift = shift_tab_w(layer);
    int g = blockIdx.x, t = threadIdx.x;
    float s = 0.f, q = 0.f;
#pragma unroll
    for (int p = 0; p < 4; ++p) {
        size_t base = ((size_t)(g * 4 + p)) * 1024;
        s += g_part2[base + t];
        q += g_part2[base + 512 + t];
    }
    float cnt = fmaxf((float)(g_end[g] - g_start[g]), 1.f);
    float mean = s / cnt;
    float m2 = mean * ms[t];
    float var = q / cnt - 2.f * m2 * mean + m2 * m2;
    float sc = w[t] * rsqrtf(var + EPSV);
    scale[(size_t)g * dim + t] = sc;
    shift[(size_t)g * dim + t] = b[t] - m2 * sc;
}

// ---------------- global stats (gn3) ----------------
__global__ void glob_partial(int x_id, int M) {
    const float* __restrict__ x = resolve_in(nullptr, x_id);
    int t = threadIdx.x;
    float s = 0.f, q = 0.f;
    for (int r = blockIdx.x; r < M; r += gridDim.x) {
        float v = x[(size_t)r * 256 + t];
        s += v;
        q += v * v;
    }
    g_part[blockIdx.x * 512 + t] = s;
    g_part[blockIdx.x * 512 + 256 + t] = q;
}

__global__ void glob_final(const float* __restrict__ w, const float* __restrict__ b,
                           const float* __restrict__ ms, int nb, int M) {
    int t = threadIdx.x;
    float s = 0.f, q = 0.f;
    for (int i = 0; i < nb; ++i) {
        s += g_part[i * 512 + t];
        q += g_part[i * 512 + 256 + t];
    }
    float mean = s / (float)M;
    float m2 = mean * ms[t];
    float var = q / (float)M - 2.f * m2 * mean + m2 * m2;
    float sc = w[t] * rsqrtf(var + EPSV);
    g_scale3[t] = sc;
    g_shift3[t] = b[t] - m2 * sc;
}

// ---------------- fused norm/prelu GEMM + bias/residual epilogue ----------------
// out[m,n] = epi( sum_k prelu(A[m,k]*scale[g,k]+shift[g,k]) * W[n,k] + bias[n] )
__global__ __launch_bounds__(256, 2)
void gemm_tc(const float* Ap, int A_id, const int* __restrict__ batch,
             int layer, int gstride, const float* __restrict__ alphaP,
             const float* __restrict__ W, const float* __restrict__ bias,
             int res_id, float* outp, int out_id, int M, int N, int K) {
    extern __shared__ char dynraw[];
    char* base = (char*)(((uintptr_t)dynraw + 1023) & ~(uintptr_t)1023);
    __shared__ int s_rowg[TM];

    const float* __restrict__ A = resolve_in(Ap, A_id);
    const float* __restrict__ scale = scale_tab(layer);
    const float* __restrict__ shift = shift_tab(layer);
    const float* res = res_id ? resolve_in(nullptr, res_id) : nullptr;
    float* out = resolve_out(outp, out_id);

    const int tid = threadIdx.x;
    const int lane = tid & 31;
    const int warp = tid >> 5;
    const int bm = blockIdx.y * TM;
    const int bn = blockIdx.x * TN;
    const bool use_prelu = (alphaP != nullptr);
    const float alpha = use_prelu ? *alphaP : 0.f;

    if (tid < TM) {
        int m = bm + tid;
        int g = batch[m < M ? m : (M - 1)];
        s_rowg[tid] = (g >= 0 && g < NGRAPH) ? g : 0;
    }

#if TC5
    // ================= tcgen05 path =================
    __shared__ uint32_t s_tmem[1];
    __shared__ __align__(8) uint64_t s_mbar[2];
    const uint32_t dynb = smem_u32(base);
    const uint32_t mbar0 = smem_u32(&s_mbar[0]);

    if (warp == 0) {
        TCGEN05_ALLOC(smem_u32(&s_tmem[0]), 128);
        TCGEN05_RELINQ();
    }
    if (tid == 0) { MBARRIER_INIT(mbar0, 1); MBARRIER_INIT(mbar0 + 8, 1); }
    __syncthreads();
    const uint32_t tmem = s_tmem[0];

    int ph0 = 0, ph1 = 0;
    const int KT = K / 32;
    for (int s = 0; s < KT; ++s) {
        const int buf = s & 1;
        char* ab = base + buf * TC_STAGE;
        char* bb = ab + 16384;
        if (s >= 2) {
            if (buf == 0) { MBARRIER_WAIT_PARITY(mbar0, ph0); ph0 ^= 1; }
            else          { MBARRIER_WAIT_PARITY(mbar0 + 8, ph1); ph1 ^= 1; }
        }
        const int kbase = s * 32;
        // A: 128x32, 4 float4 per thread, normalize+prelu+tf32
#pragma unroll
        for (int it = 0; it < 4; ++it) {
            int idx = it * 256 + tid;
            int row = idx >> 3;
            int kl = (idx & 7) * 4;
            int rg = bm + row; if (rg >= M) rg = M - 1;
            float4 v = *reinterpret_cast<const float4*>(A + (size_t)rg * K + kbase + kl);
            int g = s_rowg[row];
            float4 sc = *reinterpret_cast<const float4*>(scale + (size_t)g * gstride + kbase + kl);
            float4 sh = *reinterpret_cast<const float4*>(shift + (size_t)g * gstride + kbase + kl);
            float4 o;
            o.x = fmaf(v.x, sc.x, sh.x);
            o.y = fmaf(v.y, sc.y, sh.y);
            o.z = fmaf(v.z, sc.z, sh.z);
            o.w = fmaf(v.w, sc.w, sh.w);
            if (use_prelu) {
                o.x = o.x >= 0.f ? o.x : alpha * o.x;
                o.y = o.y >= 0.f ? o.y : alpha * o.y;
                o.z = o.z >= 0.f ? o.z : alpha * o.z;
                o.w = o.w >= 0.f ? o.w : alpha * o.w;
            }
            uint4 t;
            t.x = f2tf32(o.x); t.y = f2tf32(o.y); t.z = f2tf32(o.z); t.w = f2tf32(o.w);
            *reinterpret_cast<uint4*>(ab + tile_off32(row, kl)) = t;
        }
        // B: weights
#pragma unroll
        for (int it = 0; it < 4; ++it) {
            int idx = it * 256 + tid;
            int row = idx >> 3;
            int kl = (idx & 7) * 4;
            float4 v = *reinterpret_cast<const float4*>(W + (size_t)(bn + row) * K + kbase + kl);
            uint4 t;
            t.x = f2tf32(v.x); t.y = f2tf32(v.y); t.z = f2tf32(v.z); t.w = f2tf32(v.w);
            *reinterpret_cast<uint4*>(bb + tile_off32(row, kl)) = t;
        }
        __syncthreads();
        if (tid == 0) {
            asm volatile("fence.proxy.async.shared::cta;" ::: "memory");
            uint64_t ad = MAKE_SMEM_DESC(dynb + buf * TC_STAGE);
            uint64_t bd = MAKE_SMEM_DESC(dynb + buf * TC_STAGE + 16384);
#pragma unroll
            for (int j = 0; j < 4; ++j)
                mma_tf32_ss(tmem, ad + j * 2, bd + j * 2, IDESC_TF32, (s > 0) || (j > 0));
            TCGEN05_COMMIT(mbar0 + buf * 8);
        }
    }
    {
        const int fb = (KT - 1) & 1;
        if (fb == 0) { MBARRIER_WAIT_PARITY(mbar0, ph0); }
        else         { MBARRIER_WAIT_PARITY(mbar0 + 8, ph1); }
    }
    TCGEN05_FENCE_AFTER();

    // epilogue: 8 warps; warp w handles rows 32*(w&3).., col-blocks {2*(w>>2), 2*(w>>2)+1}
    {
        int rg = bm + (warp & 3) * 32 + lane;
        int cb0 = (warp >> 2) * 2;
#pragma unroll
        for (int cc = 0; cc < 2; ++cc) {
            int cb = cb0 + cc;
            uint32_t regs[32];
            LDTM_X32(regs, tmem + cb * 32);
            TCGEN05_WAIT_LD();
            if (rg < M) {
#pragma unroll
                for (int q = 0; q < 8; ++q) {
                    int c = bn + cb * 32 + q * 4;
                    float4 bv = *reinterpret_cast<const float4*>(bias + c);
                    float4 o;
                    o.x = __uint_as_float(regs[q * 4 + 0]) + bv.x;
                    o.y = __uint_as_float(regs[q * 4 + 1]) + bv.y;
                    o.z = __uint_as_float(regs[q * 4 + 2]) + bv.z;
                    o.w = __uint_as_float(regs[q * 4 + 3]) + bv.w;
                    if (res) {
                        float4 rr = *reinterpret_cast<const float4*>(res + (size_t)rg * N + c);
                        o.x = (o.x + rr.x) * 0.5f;
                        o.y = (o.y + rr.y) * 0.5f;
                        o.z = (o.z + rr.z) * 0.5f;
                        o.w = (o.w + rr.w) * 0.5f;
                    }
                    *reinterpret_cast<float4*>(out + (size_t)rg * N + c) = o;
                }
            }
        }
        TCGEN05_FENCE_BEFORE();
    }
    __syncthreads();
    if (warp == 0) TCGEN05_DEALLOC(tmem, 128);

#else
    // ================= mma.sync fallback path =================
    unsigned* Asb[2] = {(unsigned*)base, (unsigned*)(base + 10240)};
    unsigned* Bsb[2] = {(unsigned*)(base + 20480), (unsigned*)(base + 30720)};

    const int wm = (warp >> 1) * 32;
    const int wn = (warp & 1) * 64;
    const int qid = lane >> 2;
    const int tig = lane & 3;
    __syncthreads();

    float4 av[2], bv[2];
    auto fetch = [&](int kt) {
#pragma unroll
        for (int i = 0; i < 2; ++i) {
            int f4 = tid + i * 256;
            int r = f4 >> 2, c4 = f4 & 3;
            int k = kt * BK + c4 * 4;
            int m = bm + r;
            float4 v = make_float4(0.f, 0.f, 0.f, 0.f);
            if (m < M) v = *reinterpret_cast<const float4*>(A + (size_t)m * K + k);
            int g = s_rowg[r];
            float4 sc = *reinterpret_cast<const float4*>(scale + (size_t)g * gstride + k);
            float4 sh = *reinterpret_cast<const float4*>(shift + (size_t)g * gstride + k);
            float4 o;
            o.x = fmaf(v.x, sc.x, sh.x);
            o.y = fmaf(v.y, sc.y, sh.y);
            o.z = fmaf(v.z, sc.z, sh.z);
            o.w = fmaf(v.w, sc.w, sh.w);
            if (use_prelu) {
                o.x = o.x >= 0.f ? o.x : alpha * o.x;
                o.y = o.y >= 0.f ? o.y : alpha * o.y;
                o.z = o.z >= 0.f ? o.z : alpha * o.z;
                o.w = o.w >= 0.f ? o.w : alpha * o.w;
            }
            av[i] = o;
            bv[i] = *reinterpret_cast<const float4*>(W + (size_t)(bn + r) * K + k);
        }
    };
    auto store = [&](int buf) {
#pragma unroll
        for (int i = 0; i < 2; ++i) {
            int f4 = tid + i * 256;
            int r = f4 >> 2, c4 = f4 & 3;
            uint4 pa, pb;
            pa.x = f2tf32(av[i].x); pa.y = f2tf32(av[i].y);
            pa.z = f2tf32(av[i].z); pa.w = f2tf32(av[i].w);
            pb.x = f2tf32(bv[i].x); pb.y = f2tf32(bv[i].y);
            pb.z = f2tf32(bv[i].z); pb.w = f2tf32(bv[i].w);
            *reinterpret_cast<uint4*>(&Asb[buf][r * SAS + c4 * 4]) = pa;
            *reinterpret_cast<uint4*>(&Bsb[buf][r * SAS + c4 * 4]) = pb;
        }
    };

    float acc[2][8][4];
#pragma unroll
    for (int a = 0; a < 2; ++a)
#pragma unroll
        for (int b2 = 0; b2 < 8; ++b2)
#pragma unroll
            for (int c = 0; c < 4; ++c) acc[a][b2][c] = 0.f;

    auto compute = [&](int buf) {
#pragma unroll
        for (int kk = 0; kk < 2; ++kk) {
            unsigned a[2][4];
#pragma unroll
            for (int mt = 0; mt < 2; ++mt) {
                int row = wm + mt * 16 + qid;
                a[mt][0] = Asb[buf][row * SAS + kk * 8 + tig];
                a[mt][2] = Asb[buf][row * SAS + kk * 8 + tig + 4];
                a[mt][1] = Asb[buf][(row + 8) * SAS + kk * 8 + tig];
                a[mt][3] = Asb[buf][(row + 8) * SAS + kk * 8 + tig + 4];
            }
            unsigned bf[8][2];
#pragma unroll
            for (int nt = 0; nt < 8; ++nt) {
                int col = wn + nt * 8 + qid;
                bf[nt][0] = Bsb[buf][col * SAS + kk * 8 + tig];
                bf[nt][1] = Bsb[buf][col * SAS + kk * 8 + tig + 4];
            }
#pragma unroll
            for (int mt = 0; mt < 2; ++mt)
#pragma unroll
                for (int nt = 0; nt < 8; ++nt) mma8(acc[mt][nt], a[mt], bf[nt]);
        }
    };

    fetch(0);
    store(0);
    __syncthreads();
    const int KT = K / BK;
    for (int kt = 0; kt < KT; ++kt) {
        if (kt + 1 < KT) fetch(kt + 1);
        compute(kt & 1);
        if (kt + 1 < KT) store((kt + 1) & 1);
        __syncthreads();
    }

#pragma unroll
    for (int mt = 0; mt < 2; ++mt) {
        int r0 = bm + wm + mt * 16 + qid;
        int r1 = r0 + 8;
#pragma unroll
        for (int nt = 0; nt < 8; ++nt) {
            int c = bn + wn + nt * 8 + tig * 2;
            float2 b2 = *reinterpret_cast<const float2*>(bias + c);
            if (r0 < M) {
                float v0 = acc[mt][nt][0] + b2.x;
                float v1 = acc[mt][nt][1] + b2.y;
                if (res) {
                    float2 rr = *reinterpret_cast<const float2*>(res + (size_t)r0 * N + c);
                    v0 = (v0 + rr.x) * 0.5f;
                    v1 = (v1 + rr.y) * 0.5f;
                }
                *reinterpret_cast<float2*>(out + (size_t)r0 * N + c) = make_float2(v0, v1);
            }
            if (r1 < M) {
                float v0 = acc[mt][nt][2] + b2.x;
                float v1 = acc[mt][nt][3] + b2.y;
                if (res) {
                    float2 rr = *reinterpret_cast<const float2*>(res + (size_t)r1 * N + c);
                    v0 = (v0 + rr.x) * 0.5f;
                    v1 = (v1 + rr.y) * 0.5f;
                }
                *reinterpret_cast<float2*>(out + (size_t)r1 * N + c) = make_float2(v0, v1);
            }
        }
    }
#endif
}

// ---------------- launch ----------------
extern "C" void kernel_launch(void* const* d_in, const int* in_sizes, int n_in,
                              void* d_out, int out_size) {
    const float* x = (const float*)d_in[0];
    const int* batch = (const int*)d_in[1];
    const float* gn1_w = (const float*)d_in[2];
    const float* gn1_b = (const float*)d_in[3];
    const float* gn1_ms = (const float*)d_in[4];
    const float* gn2_w = (const float*)d_in[5];
    const float* gn2_b = (const float*)d_in[6];
    const float* gn2_ms = (const float*)d_in[7];
    const float* gn3_w = (const float*)d_in[8];
    const float* gn3_b = (const float*)d_in[9];
    const float* gn3_ms = (const float*)d_in[10];
    const float* gn4_w = (const float*)d_in[11];
    const float* gn4_b = (const float*)d_in[12];
    const float* gn4_ms = (const float*)d_in[13];
    const float* gn5_w = (const float*)d_in[14];
    const float* gn5_b = (const float*)d_in[15];
    const float* gn5_ms = (const float*)d_in[16];
    const float* lin1_W = (const float*)d_in[17];
    const float* lin1_b = (const float*)d_in[18];
    const float* lin2_W = (const float*)d_in[19];
    const float* lin2_b = (const float*)d_in[20];
    const float* lin3_W = (const float*)d_in[21];
    const float* lin3_b = (const float*)d_in[22];
    const float* lin4_W = (const float*)d_in[23];
    const float* lin4_b = (const float*)d_in[24];
    const float* lin5_W = (const float*)d_in[25];
    const float* lin5_b = (const float*)d_in[26];
    const float* a2 = (const float*)d_in[27];
    const float* a3 = (const float*)d_in[28];
    const float* a4 = (const float*)d_in[29];
    const float* a5 = (const float*)d_in[30];

    const int M = in_sizes[0] / 512;

    static bool attr_done = false;
    if (!attr_done) {
        cudaFuncSetAttribute(gemm_tc, cudaFuncAttributeMaxDynamicSharedMemorySize, DYN_SMEM);
        attr_done = true;
    }

    seg_bounds_init<<<1, NGRAPH>>>();
    seg_bounds<<<(M + 255) / 256, 256>>>(batch, M);

    const int gy = (M + TM - 1) / TM;

    // layer 1: gn1 -> lin1   (x -> s1)
    seg_stats_part<<<dim3(NGRAPH, 4), 512>>>(x, 0, 512);
    seg_stats_final<<<NGRAPH, 512>>>(gn1_w, gn1_b, gn1_ms, 1, 512);
    gemm_tc<<<dim3(2, gy), 256, DYN_SMEM>>>(x, 0, batch, 1, 512, nullptr,
                                            lin1_W, lin1_b, 0, nullptr, 1, M, 256, 512);

    // layer 2: gn2 -> prelu -> lin2   (s1 -> s2)
    seg_stats_part<<<dim3(NGRAPH, 4), 256>>>(nullptr, 1, 256);
    seg_stats_final<<<NGRAPH, 256>>>(gn2_w, gn2_b, gn2_ms, 2, 256);
    gemm_tc<<<dim3(2, gy), 256, DYN_SMEM>>>(nullptr, 1, batch, 2, 256, a2,
                                            lin2_W, lin2_b, 0, nullptr, 2, M, 256, 256);

    // layer 3: gn3 (global) -> prelu -> lin3, (h + x1)/2   (s2 -> s1, res s1)
    glob_partial<<<128, 256>>>(2, M);
    glob_final<<<1, 256>>>(gn3_w, gn3_b, gn3_ms, 128, M);
    gemm_tc<<<dim3(2, gy), 256, DYN_SMEM>>>(nullptr, 2, batch, 3, 0, a3,
                                            lin3_W, lin3_b, 1, nullptr, 1, M, 256, 256);

    // layer 4: gn4 -> prelu -> lin4, (h + x2)/2   (s1 -> s2, res s1)
    seg_stats_part<<<dim3(NGRAPH, 4), 256>>>(nullptr, 1, 256);
    seg_stats_final<<<NGRAPH, 256>>>(gn4_w, gn4_b, gn4_ms, 4, 256);
    gemm_tc<<<dim3(2, gy), 256, DYN_SMEM>>>(nullptr, 1, batch, 4, 256, a4,
                                            lin4_W, lin4_b, 1, nullptr, 2, M, 256, 256);

    // layer 5: gn5 -> prelu -> lin5   (s2 -> d_out)
    seg_stats_part<<<dim3(NGRAPH, 4), 256>>>(nullptr, 2, 256);
    seg_stats_final<<<NGRAPH, 256>>>(gn5_w, gn5_b, gn5_ms, 5, 256);
    gemm_tc<<<dim3(4, gy), 256, DYN_SMEM>>>(nullptr, 2, batch, 5, 256, a5,
                                            lin5_W, lin5_b, 0, (float*)d_out, 0, M, 512, 256);
}

// round 10
// speedup vs baseline: 1.2722x; 1.1107x over previous
#include <cuda_runtime.h>
#include <cstdint>

#define EPSV 1e-5f
#define NGRAPH 256
#define MAXM 100096

#define TM 128
#define TN 128
#define BK 32
#define SAS 36                    // padded row stride in words for BK=32 tiles
#define TILE_BYTES (128 * SAS * 4)  // 18432
#define DYN_SMEM (4 * TILE_BYTES + 1024)

// ---------------- scratch (device globals; no allocations) ----------------
__device__ int g_start[NGRAPH];
__device__ int g_end[NGRAPH];
__device__ __align__(16) float g_scale1[NGRAPH * 512];
__device__ __align__(16) float g_shift1[NGRAPH * 512];
__device__ __align__(16) float g_scale2[NGRAPH * 256];
__device__ __align__(16) float g_shift2[NGRAPH * 256];
__device__ __align__(16) float g_scale3[256];
__device__ __align__(16) float g_shift3[256];
__device__ __align__(16) float g_scale4[NGRAPH * 256];
__device__ __align__(16) float g_shift4[NGRAPH * 256];
__device__ __align__(16) float g_scale5[NGRAPH * 256];
__device__ __align__(16) float g_shift5[NGRAPH * 256];
__device__ __align__(16) float g_part[512 * 512];
__device__ __align__(16) float g_part2[NGRAPH * 4 * 1024];
__device__ __align__(16) unsigned g_Wt[512 * 256];
__device__ __align__(16) float g_s1[(size_t)MAXM * 256];
__device__ __align__(16) float g_s2[(size_t)MAXM * 256];

__device__ __forceinline__ const float* resolve_in(const float* p, int id) {
    if (id == 1) return g_s1;
    if (id == 2) return g_s2;
    return p;
}
__device__ __forceinline__ float* resolve_out(float* p, int id) {
    if (id == 1) return g_s1;
    if (id == 2) return g_s2;
    return p;
}
__device__ __forceinline__ const float* scale_tab(int layer) {
    switch (layer) {
        case 1: return g_scale1;
        case 2: return g_scale2;
        case 3: return g_scale3;
        case 4: return g_scale4;
        default: return g_scale5;
    }
}
__device__ __forceinline__ const float* shift_tab(int layer) {
    switch (layer) {
        case 1: return g_shift1;
        case 2: return g_shift2;
        case 3: return g_shift3;
        case 4: return g_shift4;
        default: return g_shift5;
    }
}
__device__ __forceinline__ float* scale_tab_w(int layer) {
    switch (layer) {
        case 1: return g_scale1;
        case 2: return g_scale2;
        case 3: return g_scale3;
        case 4: return g_scale4;
        default: return g_scale5;
    }
}
__device__ __forceinline__ float* shift_tab_w(int layer) {
    switch (layer) {
        case 1: return g_shift1;
        case 2: return g_shift2;
        case 3: return g_shift3;
        case 4: return g_shift4;
        default: return g_shift5;
    }
}

// ---------------- helpers ----------------
__device__ __forceinline__ uint32_t smem_u32(const void* p) {
    uint32_t a;
    asm("{ .reg .u64 t; cvta.to.shared.u64 t, %1; cvt.u32.u64 %0, t; }" : "=r"(a) : "l"(p));
    return a;
}
__device__ __forceinline__ unsigned f2tf32(float f) {
    unsigned r;
    asm("cvt.rna.tf32.f32 %0, %1;" : "=r"(r) : "f"(f));
    return r;
}
__device__ __forceinline__ void mma8(float c[4], const unsigned a[4], const unsigned b[2]) {
    asm volatile(
        "mma.sync.aligned.m16n8k8.row.col.f32.tf32.tf32.f32 "
        "{%0,%1,%2,%3}, {%4,%5,%6,%7}, {%8,%9}, {%0,%1,%2,%3};\n"
        : "+f"(c[0]), "+f"(c[1]), "+f"(c[2]), "+f"(c[3])
        : "r"(a[0]), "r"(a[1]), "r"(a[2]), "r"(a[3]), "r"(b[0]), "r"(b[1]));
}
__device__ __forceinline__ void cp16(uint32_t dst, const void* src) {
    asm volatile("cp.async.cg.shared.global [%0], [%1], 16;" :: "r"(dst), "l"(src));
}
#define CP_COMMIT() asm volatile("cp.async.commit_group;" ::: "memory")
#define CP_WAIT0()  asm volatile("cp.async.wait_group 0;" ::: "memory")

// ---------------- segment bounds ----------------
__global__ void seg_bounds_init() {
    int t = threadIdx.x;
    if (t < NGRAPH) { g_start[t] = 0; g_end[t] = 0; }
}

__global__ void seg_bounds(const int* __restrict__ batch, int n) {
    int i = blockIdx.x * blockDim.x + threadIdx.x;
    if (i >= n) return;
    int g = batch[i];
    if (g < 0 || g >= NGRAPH) return;
    if (i == 0 || batch[i - 1] != g) g_start[g] = i;
    if (i == n - 1 || batch[i + 1] != g) g_end[g] = i + 1;
}

// ---------------- per-graph stats: 4-way split partial + combine ----------------
__global__ void seg_stats_part(const float* xp, int x_id, int dim) {
    const float* __restrict__ x = resolve_in(xp, x_id);
    int g = blockIdx.x, part = blockIdx.y, t = threadIdx.x;
    int s0 = g_start[g], e0 = g_end[g];
    int len = e0 - s0;
    int chunk = (len + 3) >> 2;
    int r0 = s0 + part * chunk;
    int r1 = r0 + chunk; if (r1 > e0) r1 = e0;
    float s = 0.f, q = 0.f;
    for (int r = r0; r < r1; ++r) {
        float v = x[(size_t)r * dim + t];
        s += v;
        q += v * v;
    }
    size_t base = ((size_t)(g * 4 + part)) * 1024;
    g_part2[base + t] = s;
    g_part2[base + 512 + t] = q;
}

__global__ void seg_stats_final(const float* __restrict__ w, const float* __restrict__ b,
                                const float* __restrict__ ms, int layer, int dim) {
    float* __restrict__ scale = scale_tab_w(layer);
    float* __restrict__ shift = shift_tab_w(layer);
    int g = blockIdx.x, t = threadIdx.x;
    float s = 0.f, q = 0.f;
#pragma unroll
    for (int p = 0; p < 4; ++p) {
        size_t base = ((size_t)(g * 4 + p)) * 1024;
        s += g_part2[base + t];
        q += g_part2[base + 512 + t];
    }
    float cnt = fmaxf((float)(g_end[g] - g_start[g]), 1.f);
    float mean = s / cnt;
    float m2 = mean * ms[t];
    float var = q / cnt - 2.f * m2 * mean + m2 * m2;
    float sc = w[t] * rsqrtf(var + EPSV);
    scale[(size_t)g * dim + t] = sc;
    shift[(size_t)g * dim + t] = b[t] - m2 * sc;
}

// ---------------- global stats (gn3) ----------------
__global__ void glob_partial(int x_id, int M) {
    const float* __restrict__ x = resolve_in(nullptr, x_id);
    int t = threadIdx.x;
    float s = 0.f, q = 0.f;
    for (int r = blockIdx.x; r < M; r += gridDim.x) {
        float v = x[(size_t)r * 256 + t];
        s += v;
        q += v * v;
    }
    g_part[blockIdx.x * 512 + t] = s;
    g_part[blockIdx.x * 512 + 256 + t] = q;
}

__global__ void glob_final(const float* __restrict__ w, const float* __restrict__ b,
                           const float* __restrict__ ms, int nb, int M) {
    int t = threadIdx.x;
    float s = 0.f, q = 0.f;
    for (int i = 0; i < nb; ++i) {
        s += g_part[i * 512 + t];
        q += g_part[i * 512 + 256 + t];
    }
    float mean = s / (float)M;
    float m2 = mean * ms[t];
    float var = q / (float)M - 2.f * m2 * mean + m2 * m2;
    float sc = w[t] * rsqrtf(var + EPSV);
    g_scale3[t] = sc;
    g_shift3[t] = b[t] - m2 * sc;
}

// ---------------- weight pre-conversion to tf32 ----------------
__global__ void w_conv(const float* __restrict__ W, int n) {
    int i = blockIdx.x * 256 + threadIdx.x;
    if (i < n) g_Wt[i] = f2tf32(W[i]);
}

// ---------------- fused norm/prelu tf32 GEMM (mma.sync) ----------------
// out[m,n] = epi( sum_k prelu(A[m,k]*scale[g,k]+shift[g,k]) * Wt[n,k] + bias[n] )
__global__ __launch_bounds__(256, 2)
void gemm_tc(const float* Ap, int A_id, const int* __restrict__ batch,
             int layer, int gstride, const float* __restrict__ alphaP,
             const float* __restrict__ bias,
             int res_id, float* outp, int out_id, int M, int N, int K) {
    extern __shared__ char dynraw[];
    char* base = (char*)(((uintptr_t)dynraw + 1023) & ~(uintptr_t)1023);
    unsigned* Asb[2] = {(unsigned*)base, (unsigned*)(base + TILE_BYTES)};
    unsigned* Bsb[2] = {(unsigned*)(base + 2 * TILE_BYTES), (unsigned*)(base + 3 * TILE_BYTES)};
    __shared__ int s_rowg[TM];

    const float* __restrict__ A = resolve_in(Ap, A_id);
    const float* __restrict__ scale = scale_tab(layer);
    const float* __restrict__ shift = shift_tab(layer);
    const float* res = res_id ? resolve_in(nullptr, res_id) : nullptr;
    float* out = resolve_out(outp, out_id);

    const int tid = threadIdx.x;
    const int lane = tid & 31;
    const int warp = tid >> 5;
    const int bm = blockIdx.y * TM;
    const int bn = blockIdx.x * TN;
    const bool use_prelu = (alphaP != nullptr);
    const float alpha = use_prelu ? *alphaP : 0.f;

    const uint32_t b0u = smem_u32(Bsb[0]);
    const uint32_t b1u = smem_u32(Bsb[1]);

    if (tid < TM) {
        int m = bm + tid;
        int g = batch[m < M ? m : (M - 1)];
        s_rowg[tid] = (g >= 0 && g < NGRAPH) ? g : 0;
    }
    __syncthreads();
    const bool uni = (s_rowg[0] == s_rowg[TM - 1]);
    const int g0 = s_rowg[0];

    const int wm = (warp >> 1) * 32;
    const int wn = (warp & 1) * 64;
    const int qid = lane >> 2;
    const int tig = lane & 3;

    // per-thread tile coords (4 iters x 256 threads = 128 rows x 8 float4)
    float4 av[4];

    auto cpW = [&](int s) {
        const int kbase = s * BK;
        const uint32_t dstb = (s & 1) ? b1u : b0u;
#pragma unroll
        for (int it = 0; it < 4; ++it) {
            int idx = it * 256 + tid;
            int row = idx >> 3;
            int kq = (idx & 7) * 4;
            cp16(dstb + (row * SAS + kq) * 4, g_Wt + (size_t)(bn + row) * K + kbase + kq);
        }
    };

    auto fetchA = [&](int s) {
        const int kbase = s * BK;
#pragma unroll
        for (int it = 0; it < 4; ++it) {
            int idx = it * 256 + tid;
            int row = idx >> 3;
            int kq = (idx & 7) * 4;
            int rg = bm + row; if (rg >= M) rg = M - 1;
            float4 v = *reinterpret_cast<const float4*>(A + (size_t)rg * K + kbase + kq);
            int g = uni ? g0 : s_rowg[row];
            float4 sc = *reinterpret_cast<const float4*>(scale + (size_t)g * gstride + kbase + kq);
            float4 sh = *reinterpret_cast<const float4*>(shift + (size_t)g * gstride + kbase + kq);
            float4 o;
            o.x = fmaf(v.x, sc.x, sh.x);
            o.y = fmaf(v.y, sc.y, sh.y);
            o.z = fmaf(v.z, sc.z, sh.z);
            o.w = fmaf(v.w, sc.w, sh.w);
            if (use_prelu) {
                o.x = o.x >= 0.f ? o.x : alpha * o.x;
                o.y = o.y >= 0.f ? o.y : alpha * o.y;
                o.z = o.z >= 0.f ? o.z : alpha * o.z;
                o.w = o.w >= 0.f ? o.w : alpha * o.w;
            }
            av[it] = o;
        }
    };

    auto storeA = [&](int buf) {
#pragma unroll
        for (int it = 0; it < 4; ++it) {
            int idx = it * 256 + tid;
            int row = idx >> 3;
            int kq = (idx & 7) * 4;
            uint4 t;
            t.x = f2tf32(av[it].x); t.y = f2tf32(av[it].y);
            t.z = f2tf32(av[it].z); t.w = f2tf32(av[it].w);
            *reinterpret_cast<uint4*>(&Asb[buf][row * SAS + kq]) = t;
        }
    };

    float acc[2][8][4];
#pragma unroll
    for (int a = 0; a < 2; ++a)
#pragma unroll
        for (int b2 = 0; b2 < 8; ++b2)
#pragma unroll
            for (int c = 0; c < 4; ++c) acc[a][b2][c] = 0.f;

    auto compute = [&](int buf) {
        const unsigned* As = Asb[buf];
        const unsigned* Bs = Bsb[buf];
#pragma unroll
        for (int kk = 0; kk < 4; ++kk) {
            unsigned a[2][4];
#pragma unroll
            for (int mt = 0; mt < 2; ++mt) {
                int row = wm + mt * 16 + qid;
                a[mt][0] = As[row * SAS + kk * 8 + tig];
                a[mt][2] = As[row * SAS + kk * 8 + tig + 4];
                a[mt][1] = As[(row + 8) * SAS + kk * 8 + tig];
                a[mt][3] = As[(row + 8) * SAS + kk * 8 + tig + 4];
            }
            unsigned bf[8][2];
#pragma unroll
            for (int nt = 0; nt < 8; ++nt) {
                int col = wn + nt * 8 + qid;
                bf[nt][0] = Bs[col * SAS + kk * 8 + tig];
                bf[nt][1] = Bs[col * SAS + kk * 8 + tig + 4];
            }
#pragma unroll
            for (int mt = 0; mt < 2; ++mt)
#pragma unroll
                for (int nt = 0; nt < 8; ++nt) mma8(acc[mt][nt], a[mt], bf[nt]);
        }
    };

    // prologue
    cpW(0);
    CP_COMMIT();
    fetchA(0);
    storeA(0);
    CP_WAIT0();
    __syncthreads();

    const int KT = K / BK;
    for (int s = 0; s < KT; ++s) {
        if (s + 1 < KT) {
            cpW(s + 1);
            CP_COMMIT();
            fetchA(s + 1);
        }
        compute(s & 1);
        if (s + 1 < KT) storeA((s + 1) & 1);
        CP_WAIT0();
        __syncthreads();
    }

    // epilogue
#pragma unroll
    for (int mt = 0; mt < 2; ++mt) {
        int r0 = bm + wm + mt * 16 + qid;
        int r1 = r0 + 8;
#pragma unroll
        for (int nt = 0; nt < 8; ++nt) {
            int c = bn + wn + nt * 8 + tig * 2;
            float2 b2 = *reinterpret_cast<const float2*>(bias + c);
            if (r0 < M) {
                float v0 = acc[mt][nt][0] + b2.x;
                float v1 = acc[mt][nt][1] + b2.y;
                if (res) {
                    float2 rr = *reinterpret_cast<const float2*>(res + (size_t)r0 * N + c);
                    v0 = (v0 + rr.x) * 0.5f;
                    v1 = (v1 + rr.y) * 0.5f;
                }
                *reinterpret_cast<float2*>(out + (size_t)r0 * N + c) = make_float2(v0, v1);
            }
            if (r1 < M) {
                float v0 = acc[mt][nt][2] + b2.x;
                float v1 = acc[mt][nt][3] + b2.y;
                if (res) {
                    float2 rr = *reinterpret_cast<const float2*>(res + (size_t)r1 * N + c);
                    v0 = (v0 + rr.x) * 0.5f;
                    v1 = (v1 + rr.y) * 0.5f;
                }
                *reinterpret_cast<float2*>(out + (size_t)r1 * N + c) = make_float2(v0, v1);
            }
        }
    }
}

// ---------------- launch ----------------
extern "C" void kernel_launch(void* const* d_in, const int* in_sizes, int n_in,
                              void* d_out, int out_size) {
    const float* x = (const float*)d_in[0];
    const int* batch = (const int*)d_in[1];
    const float* gn1_w = (const float*)d_in[2];
    const float* gn1_b = (const float*)d_in[3];
    const float* gn1_ms = (const float*)d_in[4];
    const float* gn2_w = (const float*)d_in[5];
    const float* gn2_b = (const float*)d_in[6];
    const float* gn2_ms = (const float*)d_in[7];
    const float* gn3_w = (const float*)d_in[8];
    const float* gn3_b = (const float*)d_in[9];
    const float* gn3_ms = (const float*)d_in[10];
    const float* gn4_w = (const float*)d_in[11];
    const float* gn4_b = (const float*)d_in[12];
    const float* gn4_ms = (const float*)d_in[13];
    const float* gn5_w = (const float*)d_in[14];
    const float* gn5_b = (const float*)d_in[15];
    const float* gn5_ms = (const float*)d_in[16];
    const float* lin1_W = (const float*)d_in[17];
    const float* lin1_b = (const float*)d_in[18];
    const float* lin2_W = (const float*)d_in[19];
    const float* lin2_b = (const float*)d_in[20];
    const float* lin3_W = (const float*)d_in[21];
    const float* lin3_b = (const float*)d_in[22];
    const float* lin4_W = (const float*)d_in[23];
    const float* lin4_b = (const float*)d_in[24];
    const float* lin5_W = (const float*)d_in[25];
    const float* lin5_b = (const float*)d_in[26];
    const float* a2 = (const float*)d_in[27];
    const float* a3 = (const float*)d_in[28];
    const float* a4 = (const float*)d_in[29];
    const float* a5 = (const float*)d_in[30];

    const int M = in_sizes[0] / 512;

    static bool attr_done = false;
    if (!attr_done) {
        cudaFuncSetAttribute(gemm_tc, cudaFuncAttributeMaxDynamicSharedMemorySize, DYN_SMEM);
        attr_done = true;
    }

    seg_bounds_init<<<1, NGRAPH>>>();
    seg_bounds<<<(M + 255) / 256, 256>>>(batch, M);

    const int gy = (M + TM - 1) / TM;

    // layer 1: gn1 -> lin1   (x -> s1)
    seg_stats_part<<<dim3(NGRAPH, 4), 512>>>(x, 0, 512);
    seg_stats_final<<<NGRAPH, 512>>>(gn1_w, gn1_b, gn1_ms, 1, 512);
    w_conv<<<512, 256>>>(lin1_W, 256 * 512);
    gemm_tc<<<dim3(2, gy), 256, DYN_SMEM>>>(x, 0, batch, 1, 512, nullptr,
                                            lin1_b, 0, nullptr, 1, M, 256, 512);

    // layer 2: gn2 -> prelu -> lin2   (s1 -> s2)
    seg_stats_part<<<dim3(NGRAPH, 4), 256>>>(nullptr, 1, 256);
    seg_stats_final<<<NGRAPH, 256>>>(gn2_w, gn2_b, gn2_ms, 2, 256);
    w_conv<<<256, 256>>>(lin2_W, 256 * 256);
    gemm_tc<<<dim3(2, gy), 256, DYN_SMEM>>>(nullptr, 1, batch, 2, 256, a2,
                                            lin2_b, 0, nullptr, 2, M, 256, 256);

    // layer 3: gn3 (global) -> prelu -> lin3, (h + x1)/2   (s2 -> s1, res s1)
    glob_partial<<<512, 256>>>(2, M);
    glob_final<<<1, 256>>>(gn3_w, gn3_b, gn3_ms, 512, M);
    w_conv<<<256, 256>>>(lin3_W, 256 * 256);
    gemm_tc<<<dim3(2, gy), 256, DYN_SMEM>>>(nullptr, 2, batch, 3, 0, a3,
                                            lin3_b, 1, nullptr, 1, M, 256, 256);

    // layer 4: gn4 -> prelu -> lin4, (h + x2)/2   (s1 -> s2, res s1)
    seg_stats_part<<<dim3(NGRAPH, 4), 256>>>(nullptr, 1, 256);
    seg_stats_final<<<NGRAPH, 256>>>(gn4_w, gn4_b, gn4_ms, 4, 256);
    w_conv<<<256, 256>>>(lin4_W, 256 * 256);
    gemm_tc<<<dim3(2, gy), 256, DYN_SMEM>>>(nullptr, 1, batch, 4, 256, a4,
                                            lin4_b, 1, nullptr, 2, M, 256, 256);

    // layer 5: gn5 -> prelu -> lin5   (s2 -> d_out)
    seg_stats_part<<<dim3(NGRAPH, 4), 256>>>(nullptr, 2, 256);
    seg_stats_final<<<NGRAPH, 256>>>(gn5_w, gn5_b, gn5_ms, 5, 256);
    w_conv<<<512, 256>>>(lin5_W, 512 * 256);
    gemm_tc<<<dim3(4, gy), 256, DYN_SMEM>>>(nullptr, 2, batch, 5, 256, a5,
                                            lin5_b, 0, (float*)d_out, 0, M, 512, 256);
}